// round 15
// baseline (speedup 1.0000x reference)
#include <cuda_runtime.h>
#include <math.h>
#include <stdint.h>

#define M_TAGS   512
#define L_SEQ    4096
#define V_VOCAB  50000
#define VP1      50001
#define NCTA     16
#define THREADS  256
#define CPW      4
#define FULLMASK 0xffffffffu

// ---- device scratch ----
__device__ float g_a0 [M_TAGS];
__device__ float g_ext[L_SEQ * M_TAGS];   // ext[t][j] = E[j, x[t]]
__device__ float g_phipath;

// ---- PTX helpers ----
__device__ __forceinline__ uint32_t smem_u32(const void* p) {
    uint32_t a;
    asm("{ .reg .u64 t; cvta.to.shared.u64 t, %1; cvt.u32.u64 %0, t; }" : "=r"(a) : "l"(p));
    return a;
}
__device__ __forceinline__ uint32_t mapa_u32(uint32_t addr, uint32_t rank) {
    uint32_t r;
    asm("mapa.shared::cluster.u32 %0, %1, %2;" : "=r"(r) : "r"(addr), "r"(rank));
    return r;
}
__device__ __forceinline__ uint32_t lds_vol_u32(uint32_t a) {
    uint32_t v;
    asm volatile("ld.volatile.shared.b32 %0, [%1];" : "=r"(v) : "r"(a));
    return v;
}
__device__ __forceinline__ float4 lds_vol_v4(uint32_t a) {
    float4 v;
    asm volatile("ld.volatile.shared.v4.f32 {%0,%1,%2,%3}, [%4];"
                 : "=f"(v.x), "=f"(v.y), "=f"(v.z), "=f"(v.w) : "r"(a));
    return v;
}
__device__ __forceinline__ void st_cluster_v4(uint32_t a, float4 v) {
    asm volatile("st.shared::cluster.v4.f32 [%0], {%1,%2,%3,%4};"
                 :: "r"(a), "f"(v.x), "f"(v.y), "f"(v.z), "f"(v.w));
}
__device__ __forceinline__ unsigned long long packdup(float x) {
    unsigned long long d; uint32_t u = __float_as_uint(x);
    asm("mov.b64 %0, {%1, %1};" : "=l"(d) : "r"(u)); return d;
}
__device__ __forceinline__ unsigned long long pack2(float x, float y) {
    unsigned long long d;
    asm("mov.b64 %0, {%1, %2};" : "=l"(d) : "r"(__float_as_uint(x)), "r"(__float_as_uint(y)));
    return d;
}
__device__ __forceinline__ void fma2(unsigned long long& d, unsigned long long a, unsigned long long b) {
    asm("fma.rn.f32x2 %0, %1, %2, %0;" : "+l"(d) : "l"(a), "l"(b));
}
__device__ __forceinline__ void add2(unsigned long long& d, unsigned long long a) {
    asm("add.rn.f32x2 %0, %0, %1;" : "+l"(d) : "l"(a));
}
__device__ __forceinline__ void unpack2(unsigned long long d, float& lo, float& hi) {
    uint32_t a, b;
    asm("mov.b64 {%0, %1}, %2;" : "=r"(a), "=r"(b) : "l"(d));
    lo = __uint_as_float(a); hi = __uint_as_float(b);
}
__device__ __forceinline__ void cluster_barrier() {
    asm volatile("barrier.cluster.arrive.aligned;" ::: "memory");
    asm volatile("barrier.cluster.wait.aligned;"   ::: "memory");
}

// =====================================================================
// Init: alpha0 -> g_a0, phi_path, ext gather
// =====================================================================
__global__ void crf_init_kernel(const float* __restrict__ T,
                                const float* __restrict__ E,
                                const float* __restrict__ Eprev,
                                const float* __restrict__ Enext,
                                const float* __restrict__ Cap,
                                const int*   __restrict__ x,
                                const int*   __restrict__ y,
                                const int*   __restrict__ upper)
{
    const int b   = blockIdx.x;
    const int tid = threadIdx.x;

    if (b == 0) {
        const int x0 = x[0], x1 = x[1], u0 = upper[0];
        for (int m = tid; m < M_TAGS; m += blockDim.x) {
            float phi = T[M_TAGS * M_TAGS + m]
                      + Eprev[m * VP1 + M_TAGS]
                      + Enext[m * VP1 + x1]
                      + Cap[m * 2 + u0]
                      + E[m * V_VOCAB + x0];
            g_a0[m] = expf(phi);
        }
    } else if (b == 1) {
        __shared__ float red[256];
        float acc = 0.f;
        for (int t = tid; t < L_SEQ; t += blockDim.x) {
            int yt = y[t];
            int yp = (t == 0)         ? M_TAGS : y[t - 1];
            int xp = (t == 0)         ? M_TAGS : x[t - 1];
            int xn = (t == L_SEQ - 1) ? M_TAGS : x[t + 1];
            acc += T[yp * M_TAGS + yt]
                 + Eprev[yt * VP1 + xp]
                 + Enext[yt * VP1 + xn]
                 + Cap[yt * 2 + upper[t]]
                 + E[yt * V_VOCAB + x[t]];
        }
        red[tid] = acc;
        __syncthreads();
        for (int s = 128; s > 0; s >>= 1) {
            if (tid < s) red[tid] += red[tid + s];
            __syncthreads();
        }
        if (tid == 0) g_phipath = red[0];
    } else {
        long long idx = (long long)(b - 2) * blockDim.x + tid;
        if (idx < (long long)L_SEQ * M_TAGS) {
            int t = (int)(idx >> 9);
            int j = (int)(idx & 511);
            g_ext[idx] = E[(long long)j * V_VOCAB + x[t]];
        }
    }
}

// ---- one chain step, phase-specialized (R13 structure) ----
// Detect: SCALAR sign-poll of the 4 group .x words (4 LDS.32/pass — 4x
// less crossbar traffic than v4 polling, keeping SMEM ports free for
// incoming DSMEM stores). After the vote passes, ONE v4 fetch per group.
#define FMAGRP(j, v)                                                          \
    fma2(a01a, packdup((v).x), tm01[4*(j)+0]); fma2(a23a, packdup((v).x), tm23[4*(j)+0]); \
    fma2(a01b, packdup((v).y), tm01[4*(j)+1]); fma2(a23b, packdup((v).y), tm23[4*(j)+1]); \
    fma2(a01a, packdup((v).z), tm01[4*(j)+2]); fma2(a23a, packdup((v).z), tm23[4*(j)+2]); \
    fma2(a01b, packdup((v).w), tm01[4*(j)+3]); fma2(a23b, packdup((v).w), tm23[4*(j)+3]);

#define STEP(PHASE, pb, extv, DO_RENORM)                                      \
do {                                                                          \
    const uint32_t ps_ = (((PHASE) == 0) ? ((pb) ^ 1u) : (pb)) << 31;         \
    const uint32_t rb_ = abase + ((((PHASE) + 3) & 3) << 11) + (lane << 4);   \
    for (;;) {                                                                \
        uint32_t w0 = lds_vol_u32(rb_);                                       \
        uint32_t w1 = lds_vol_u32(rb_ + 512);                                 \
        uint32_t w2 = lds_vol_u32(rb_ + 1024);                                \
        uint32_t w3 = lds_vol_u32(rb_ + 1536);                                \
        uint32_t yy = (w0 ^ ps_) | (w1 ^ ps_) | (w2 ^ ps_) | (w3 ^ ps_);      \
        if (__all_sync(FULLMASK, (int)yy >= 0)) break;                        \
        if (--budget < 0) break;                                              \
    }                                                                         \
    float4 v0 = lds_vol_v4(rb_);                                              \
    float4 v1 = lds_vol_v4(rb_ + 512);                                        \
    float4 v2 = lds_vol_v4(rb_ + 1024);                                       \
    float4 v3 = lds_vol_v4(rb_ + 1536);                                       \
    unsigned long long a01a = 0ull, a01b = 0ull, a23a = 0ull, a23b = 0ull;    \
    FMAGRP(0, v0); FMAGRP(1, v1); FMAGRP(2, v2); FMAGRP(3, v3);               \
    add2(a01a, a01b); add2(a23a, a23b);                                       \
    float p0, p1, p2, p3;                                                     \
    unpack2(a01a, p0, p1); unpack2(a23a, p2, p3);                             \
    float scale_;                                                             \
    if (DO_RENORM) {                                                          \
        float ssl = ((v0.x + v0.y) + (v0.z + v0.w))                           \
                  + ((v1.x + v1.y) + (v1.z + v1.w))                           \
                  + ((v2.x + v2.y) + (v2.z + v2.w))                           \
                  + ((v3.x + v3.y) + (v3.z + v3.w));                          \
        ssl += __shfl_xor_sync(FULLMASK, ssl, 16);                            \
        ssl += __shfl_xor_sync(FULLMASK, ssl, 8);                             \
        ssl += __shfl_xor_sync(FULLMASK, ssl, 4);                             \
        ssl += __shfl_xor_sync(FULLMASK, ssl, 2);                             \
        ssl += __shfl_xor_sync(FULLMASK, ssl, 1);                             \
        scale_ = ((pb) ? -0.0078125f : 0.0078125f) / ssl;                     \
        if (rank == 0 && tid == 0) log_acc += logf(fabsf(ssl));               \
    } else {                                                                  \
        scale_ = ((PHASE) == 0) ? -0.0078125f : 0.0078125f;                   \
    }                                                                         \
    float r0 = p0 * (scale_ * (extv).x);                                      \
    float r1 = p1 * (scale_ * (extv).y);                                      \
    float r2 = p2 * (scale_ * (extv).z);                                      \
    float r3 = p3 * (scale_ * (extv).w);                                      \
    r0 += __shfl_xor_sync(FULLMASK, r0, 16); r1 += __shfl_xor_sync(FULLMASK, r1, 16); \
    r2 += __shfl_xor_sync(FULLMASK, r2, 16); r3 += __shfl_xor_sync(FULLMASK, r3, 16); \
    r0 += __shfl_xor_sync(FULLMASK, r0, 8);  r1 += __shfl_xor_sync(FULLMASK, r1, 8);  \
    r2 += __shfl_xor_sync(FULLMASK, r2, 8);  r3 += __shfl_xor_sync(FULLMASK, r3, 8);  \
    r0 += __shfl_xor_sync(FULLMASK, r0, 4);  r1 += __shfl_xor_sync(FULLMASK, r1, 4);  \
    r2 += __shfl_xor_sync(FULLMASK, r2, 4);  r3 += __shfl_xor_sync(FULLMASK, r3, 4);  \
    r0 += __shfl_xor_sync(FULLMASK, r0, 2);  r1 += __shfl_xor_sync(FULLMASK, r1, 2);  \
    r2 += __shfl_xor_sync(FULLMASK, r2, 2);  r3 += __shfl_xor_sync(FULLMASK, r3, 2);  \
    r0 += __shfl_xor_sync(FULLMASK, r0, 1);  r1 += __shfl_xor_sync(FULLMASK, r1, 1);  \
    r2 += __shfl_xor_sync(FULLMASK, r2, 1);  r3 += __shfl_xor_sync(FULLMASK, r3, 1);  \
    if (lane < 16)                                                            \
        st_cluster_v4(mypeer + ((PHASE) << 11) + col_off,                     \
                      make_float4(r0, r1, r2, r3));                           \
} while (0)

// =====================================================================
// Chain: one 16-CTA cluster, 256 thr/CTA, 4 cols/warp, 4-slot SMEM ring,
// sign-parity readiness, 4x phase-specialized unroll (R13), scalar
// sign-detect + single v4 fetch (R8's crossbar lesson).
// =====================================================================
__global__ void __launch_bounds__(THREADS, 1) __cluster_dims__(NCTA, 1, 1)
crf_chain_kernel(const float* __restrict__ T, float* __restrict__ out)
{
    __shared__ float A[4][M_TAGS];     // 4-slot ring, 2KB per slot

    const int tid  = threadIdx.x;
    const int w    = tid >> 5;
    const int lane = tid & 31;
    const int rank = blockIdx.x;
    const int c0   = rank * 32 + w * CPW;

    // ---- local init: alpha0 (positive = parity 0) in slot 0 ----
    A[0][tid]       = g_a0[tid];
    A[0][tid + 256] = g_a0[tid + 256];
    A[1][tid]       = -1.f;  A[1][tid + 256] = -1.f;
    A[2][tid]       = -1.f;  A[2][tid + 256] = -1.f;
    A[3][tid]       = -1.f;  A[3][tid + 256] = -1.f;
    __syncthreads();
    cluster_barrier();

    // ---- Tm slice into registers, k matching the a-layout:
    //      av[4j+i] = a[128j + 4*lane + i]  =>  k = 128j + 4*lane + i
    unsigned long long tm01[16], tm23[16];
    #pragma unroll
    for (int j = 0; j < 4; ++j) {
        #pragma unroll
        for (int i = 0; i < 4; ++i) {
            int g = j * 4 + i;
            int k = j * 128 + lane * 4 + i;
            float4 tv = *(const float4*)(T + (long long)k * M_TAGS + c0);
            tm01[g] = pack2(tv.x, tv.y);
            tm23[g] = pack2(tv.z, tv.w);
        }
    }

    const uint32_t abase   = smem_u32(&A[0][0]);
    const uint32_t mypeer  = mapa_u32(abase, (uint32_t)(lane & 15));
    const uint32_t col_off = (uint32_t)(c0 << 2);

    float log_acc = 0.f;
    int   budget  = 1 << 25;

    // ---- ext for peel steps t=1..3 and first block t=4..7 ----
    const float* extp = g_ext + c0;
    float4 e1 = *(const float4*)(extp + 1 * M_TAGS);
    float4 e2 = *(const float4*)(extp + 2 * M_TAGS);
    float4 e3 = *(const float4*)(extp + 3 * M_TAGS);
    float4 n0 = *(const float4*)(extp + 4 * M_TAGS);
    float4 n1 = *(const float4*)(extp + 5 * M_TAGS);
    float4 n2 = *(const float4*)(extp + 6 * M_TAGS);
    float4 n3 = *(const float4*)(extp + 7 * M_TAGS);

    // ---- peel t = 1, 2, 3 (pb = 0, no renorm) ----
    STEP(1, 0u, e1, false);
    STEP(2, 0u, e2, false);
    STEP(3, 0u, e3, false);

    // ---- main blocks: u = 1..1023, t = 4u .. 4u+3 ----
    for (int u = 1; u <= 1023; ++u) {
        const uint32_t pb = (uint32_t)(u & 1);
        float4 b0 = n0, b1 = n1, b2 = n2, b3 = n3;
        if (u < 1023) {                       // prefetch next block (off-chain)
            const float* np = extp + (long long)(4 * u + 4) * M_TAGS;
            n0 = *(const float4*)(np);
            n1 = *(const float4*)(np + M_TAGS);
            n2 = *(const float4*)(np + 2 * M_TAGS);
            n3 = *(const float4*)(np + 3 * M_TAGS);
        }
        const bool renorm = ((u & 63) == 0);
        STEP(0, pb, b0, renorm);
        STEP(1, pb, b1, false);
        STEP(2, pb, b2, false);
        STEP(3, pb, b3, false);
    }

    // ---- finalize: rank 0, warp 0 (t = 4095, stored parity = 1) ----
    if (rank == 0 && w == 0) {
        const uint32_t ps = 1u << 31;
        const uint32_t rbase = abase + (3u << 11) + (lane << 4);
        for (;;) {
            uint32_t w0 = lds_vol_u32(rbase);
            uint32_t w1 = lds_vol_u32(rbase + 512);
            uint32_t w2 = lds_vol_u32(rbase + 1024);
            uint32_t w3 = lds_vol_u32(rbase + 1536);
            uint32_t yy = (w0 ^ ps) | (w1 ^ ps) | (w2 ^ ps) | (w3 ^ ps);
            if (__all_sync(FULLMASK, (int)yy >= 0)) break;
            if (--budget < 0) break;
        }
        float4 v0 = lds_vol_v4(rbase);
        float4 v1 = lds_vol_v4(rbase + 512);
        float4 v2 = lds_vol_v4(rbase + 1024);
        float4 v3 = lds_vol_v4(rbase + 1536);
        float ss = ((v0.x + v0.y) + (v0.z + v0.w))
                 + ((v1.x + v1.y) + (v1.z + v1.w))
                 + ((v2.x + v2.y) + (v2.z + v2.w))
                 + ((v3.x + v3.y) + (v3.z + v3.w));
        #pragma unroll
        for (int off = 16; off; off >>= 1)
            ss += __shfl_xor_sync(FULLMASK, ss, off);
        if (lane == 0) {
            // ln(128) = 7*ln(2) = 4.852030263919617
            double logz = (double)logf(fabsf(ss))
                        + 4095.0 * 4.852030263919617
                        + (double)log_acc;
            out[0] = (float)(logz - (double)g_phipath);
        }
    }

    // ---- exit fence ----
    cluster_barrier();
}

// =====================================================================
extern "C" void kernel_launch(void* const* d_in, const int* in_sizes, int n_in,
                              void* d_out, int out_size)
{
    const float* T     = (const float*)d_in[0];
    const float* E     = (const float*)d_in[1];
    const float* Eprev = (const float*)d_in[2];
    const float* Enext = (const float*)d_in[3];
    const float* Cap   = (const float*)d_in[4];
    const int*   x     = (const int*)d_in[5];
    const int*   y     = (const int*)d_in[6];
    const int*   upper = (const int*)d_in[7];
    float*       out   = (float*)d_out;
    (void)in_sizes; (void)n_in; (void)out_size;

    cudaFuncSetAttribute(crf_chain_kernel,
                         cudaFuncAttributeNonPortableClusterSizeAllowed, 1);

    const int ext_blocks = (L_SEQ * M_TAGS + 255) / 256;   // 8192
    crf_init_kernel<<<2 + ext_blocks, 256>>>(T, E, Eprev, Enext, Cap, x, y, upper);
    crf_chain_kernel<<<NCTA, THREADS>>>(T, out);
}

// round 16
// speedup vs baseline: 1.1234x; 1.1234x over previous
#include <cuda_runtime.h>
#include <math.h>
#include <stdint.h>

#define M_TAGS   512
#define L_SEQ    4096
#define V_VOCAB  50000
#define VP1      50001
#define NCTA     16
#define THREADS  256
#define CPW      4
#define FULLMASK 0xffffffffu

// ---- device scratch ----
__device__ float g_a0 [M_TAGS];
__device__ float g_ext[L_SEQ * M_TAGS];   // ext[t][j] = E[j, x[t]]
__device__ float g_phipath;

// ---- PTX helpers ----
__device__ __forceinline__ uint32_t smem_u32(const void* p) {
    uint32_t a;
    asm("{ .reg .u64 t; cvta.to.shared.u64 t, %1; cvt.u32.u64 %0, t; }" : "=r"(a) : "l"(p));
    return a;
}
__device__ __forceinline__ uint32_t mapa_u32(uint32_t addr, uint32_t rank) {
    uint32_t r;
    asm("mapa.shared::cluster.u32 %0, %1, %2;" : "=r"(r) : "r"(addr), "r"(rank));
    return r;
}
__device__ __forceinline__ float4 lds_vol_v4(uint32_t a) {
    float4 v;
    asm volatile("ld.volatile.shared.v4.f32 {%0,%1,%2,%3}, [%4];"
                 : "=f"(v.x), "=f"(v.y), "=f"(v.z), "=f"(v.w) : "r"(a));
    return v;
}
__device__ __forceinline__ void st_cluster_v4(uint32_t a, float4 v) {
    asm volatile("st.shared::cluster.v4.f32 [%0], {%1,%2,%3,%4};"
                 :: "r"(a), "f"(v.x), "f"(v.y), "f"(v.z), "f"(v.w));
}
__device__ __forceinline__ unsigned long long packdup(float x) {
    unsigned long long d; uint32_t u = __float_as_uint(x);
    asm("mov.b64 %0, {%1, %1};" : "=l"(d) : "r"(u)); return d;
}
__device__ __forceinline__ unsigned long long pack2(float x, float y) {
    unsigned long long d;
    asm("mov.b64 %0, {%1, %2};" : "=l"(d) : "r"(__float_as_uint(x)), "r"(__float_as_uint(y)));
    return d;
}
__device__ __forceinline__ void fma2(unsigned long long& d, unsigned long long a, unsigned long long b) {
    asm("fma.rn.f32x2 %0, %1, %2, %0;" : "+l"(d) : "l"(a), "l"(b));
}
__device__ __forceinline__ void add2(unsigned long long& d, unsigned long long a) {
    asm("add.rn.f32x2 %0, %0, %1;" : "+l"(d) : "l"(a));
}
__device__ __forceinline__ void unpack2(unsigned long long d, float& lo, float& hi) {
    uint32_t a, b;
    asm("mov.b64 {%0, %1}, %2;" : "=r"(a), "=r"(b) : "l"(d));
    lo = __uint_as_float(a); hi = __uint_as_float(b);
}
__device__ __forceinline__ void cluster_barrier() {
    asm volatile("barrier.cluster.arrive.aligned;" ::: "memory");
    asm volatile("barrier.cluster.wait.aligned;"   ::: "memory");
}

// =====================================================================
// Init: alpha0 -> g_a0, phi_path, ext gather
// =====================================================================
__global__ void crf_init_kernel(const float* __restrict__ T,
                                const float* __restrict__ E,
                                const float* __restrict__ Eprev,
                                const float* __restrict__ Enext,
                                const float* __restrict__ Cap,
                                const int*   __restrict__ x,
                                const int*   __restrict__ y,
                                const int*   __restrict__ upper)
{
    const int b   = blockIdx.x;
    const int tid = threadIdx.x;

    if (b == 0) {
        const int x0 = x[0], x1 = x[1], u0 = upper[0];
        for (int m = tid; m < M_TAGS; m += blockDim.x) {
            float phi = T[M_TAGS * M_TAGS + m]
                      + Eprev[m * VP1 + M_TAGS]
                      + Enext[m * VP1 + x1]
                      + Cap[m * 2 + u0]
                      + E[m * V_VOCAB + x0];
            g_a0[m] = expf(phi);
        }
    } else if (b == 1) {
        __shared__ float red[256];
        float acc = 0.f;
        for (int t = tid; t < L_SEQ; t += blockDim.x) {
            int yt = y[t];
            int yp = (t == 0)         ? M_TAGS : y[t - 1];
            int xp = (t == 0)         ? M_TAGS : x[t - 1];
            int xn = (t == L_SEQ - 1) ? M_TAGS : x[t + 1];
            acc += T[yp * M_TAGS + yt]
                 + Eprev[yt * VP1 + xp]
                 + Enext[yt * VP1 + xn]
                 + Cap[yt * 2 + upper[t]]
                 + E[yt * V_VOCAB + x[t]];
        }
        red[tid] = acc;
        __syncthreads();
        for (int s = 128; s > 0; s >>= 1) {
            if (tid < s) red[tid] += red[tid + s];
            __syncthreads();
        }
        if (tid == 0) g_phipath = red[0];
    } else {
        long long idx = (long long)(b - 2) * blockDim.x + tid;
        if (idx < (long long)L_SEQ * M_TAGS) {
            int t = (int)(idx >> 9);
            int j = (int)(idx & 511);
            g_ext[idx] = E[(long long)j * V_VOCAB + x[t]];
        }
    }
}

// ---- one chain step, phase-specialized via macro (regs stay regs) ----
// PHASE = t & 3 (compile-time). pb = (t>>2)&1 at PHASE>0; incoming parity
// pr = pb except PHASE==0 where pr = pb^1. Non-renorm scale: +1/128 except
// PHASE==0 (parity flip) -> -1/128. RENORM only possible at PHASE==0.
#define FMAGRP(j, v)                                                          \
    fma2(a01a, packdup((v).x), tm01[4*(j)+0]); fma2(a23a, packdup((v).x), tm23[4*(j)+0]); \
    fma2(a01b, packdup((v).y), tm01[4*(j)+1]); fma2(a23b, packdup((v).y), tm23[4*(j)+1]); \
    fma2(a01a, packdup((v).z), tm01[4*(j)+2]); fma2(a23a, packdup((v).z), tm23[4*(j)+2]); \
    fma2(a01b, packdup((v).w), tm01[4*(j)+3]); fma2(a23b, packdup((v).w), tm23[4*(j)+3]);

#define STEP(PHASE, pb, extv, DO_RENORM)                                      \
do {                                                                          \
    const uint32_t ps_ = (((PHASE) == 0) ? ((pb) ^ 1u) : (pb)) << 31;         \
    const uint32_t rb_ = abase + ((((PHASE) + 3) & 3) << 11) + (lane << 4);   \
    float4 v0, v1, v2, v3;                                                    \
    for (;;) {                                                                \
        v0 = lds_vol_v4(rb_);                                                 \
        v1 = lds_vol_v4(rb_ + 512);                                           \
        v2 = lds_vol_v4(rb_ + 1024);                                          \
        v3 = lds_vol_v4(rb_ + 1536);                                          \
        uint32_t yy = (__float_as_uint(v0.x) ^ ps_) | (__float_as_uint(v1.x) ^ ps_) \
                    | (__float_as_uint(v2.x) ^ ps_) | (__float_as_uint(v3.x) ^ ps_); \
        if (__all_sync(FULLMASK, (int)yy >= 0)) break;                        \
        if (--budget < 0) break;                                              \
    }                                                                         \
    unsigned long long a01a = 0ull, a01b = 0ull, a23a = 0ull, a23b = 0ull;    \
    FMAGRP(0, v0); FMAGRP(1, v1); FMAGRP(2, v2); FMAGRP(3, v3);               \
    add2(a01a, a01b); add2(a23a, a23b);                                       \
    float p0, p1, p2, p3;                                                     \
    unpack2(a01a, p0, p1); unpack2(a23a, p2, p3);                             \
    float scale_;                                                             \
    if (DO_RENORM) {                                                          \
        float ssl = ((v0.x + v0.y) + (v0.z + v0.w))                           \
                  + ((v1.x + v1.y) + (v1.z + v1.w))                           \
                  + ((v2.x + v2.y) + (v2.z + v2.w))                           \
                  + ((v3.x + v3.y) + (v3.z + v3.w));                          \
        ssl += __shfl_xor_sync(FULLMASK, ssl, 16);                            \
        ssl += __shfl_xor_sync(FULLMASK, ssl, 8);                             \
        ssl += __shfl_xor_sync(FULLMASK, ssl, 4);                             \
        ssl += __shfl_xor_sync(FULLMASK, ssl, 2);                             \
        ssl += __shfl_xor_sync(FULLMASK, ssl, 1);                             \
        scale_ = ((pb) ? -0.0078125f : 0.0078125f) / ssl;                     \
        if (rank == 0 && tid == 0) log_acc += logf(fabsf(ssl));               \
    } else {                                                                  \
        scale_ = ((PHASE) == 0) ? -0.0078125f : 0.0078125f;                   \
    }                                                                         \
    float r0 = p0 * (scale_ * (extv).x);                                      \
    float r1 = p1 * (scale_ * (extv).y);                                      \
    float r2 = p2 * (scale_ * (extv).z);                                      \
    float r3 = p3 * (scale_ * (extv).w);                                      \
    r0 += __shfl_xor_sync(FULLMASK, r0, 16); r1 += __shfl_xor_sync(FULLMASK, r1, 16); \
    r2 += __shfl_xor_sync(FULLMASK, r2, 16); r3 += __shfl_xor_sync(FULLMASK, r3, 16); \
    r0 += __shfl_xor_sync(FULLMASK, r0, 8);  r1 += __shfl_xor_sync(FULLMASK, r1, 8);  \
    r2 += __shfl_xor_sync(FULLMASK, r2, 8);  r3 += __shfl_xor_sync(FULLMASK, r3, 8);  \
    r0 += __shfl_xor_sync(FULLMASK, r0, 4);  r1 += __shfl_xor_sync(FULLMASK, r1, 4);  \
    r2 += __shfl_xor_sync(FULLMASK, r2, 4);  r3 += __shfl_xor_sync(FULLMASK, r3, 4);  \
    r0 += __shfl_xor_sync(FULLMASK, r0, 2);  r1 += __shfl_xor_sync(FULLMASK, r1, 2);  \
    r2 += __shfl_xor_sync(FULLMASK, r2, 2);  r3 += __shfl_xor_sync(FULLMASK, r3, 2);  \
    r0 += __shfl_xor_sync(FULLMASK, r0, 1);  r1 += __shfl_xor_sync(FULLMASK, r1, 1);  \
    r2 += __shfl_xor_sync(FULLMASK, r2, 1);  r3 += __shfl_xor_sync(FULLMASK, r3, 1);  \
    if (lane < 16)                                                            \
        st_cluster_v4(mypeer + ((PHASE) << 11) + col_off,                     \
                      make_float4(r0, r1, r2, r3));                           \
} while (0)

// =====================================================================
// Chain: one 16-CTA cluster, 256 thr/CTA, 4 cols/warp, 4-slot SMEM ring,
// sign-parity readiness. Loop unrolled by 4 (phase-specialized bodies:
// constant slots/scales; renorm test only in phase-0). Poll fused with
// data fetch. Next block's ext prefetched a whole block ahead.
// =====================================================================
__global__ void __launch_bounds__(THREADS, 1) __cluster_dims__(NCTA, 1, 1)
crf_chain_kernel(const float* __restrict__ T, float* __restrict__ out)
{
    __shared__ float A[4][M_TAGS];     // 4-slot ring, 2KB per slot

    const int tid  = threadIdx.x;
    const int w    = tid >> 5;
    const int lane = tid & 31;
    const int rank = blockIdx.x;
    const int c0   = rank * 32 + w * CPW;

    // ---- local init: alpha0 (positive = parity 0) in slot 0 ----
    A[0][tid]       = g_a0[tid];
    A[0][tid + 256] = g_a0[tid + 256];
    A[1][tid]       = -1.f;  A[1][tid + 256] = -1.f;
    A[2][tid]       = -1.f;  A[2][tid + 256] = -1.f;
    A[3][tid]       = -1.f;  A[3][tid + 256] = -1.f;
    __syncthreads();
    cluster_barrier();

    // ---- Tm slice into registers, k matching the a-layout:
    //      av[4j+i] = a[128j + 4*lane + i]  =>  k = 128j + 4*lane + i
    unsigned long long tm01[16], tm23[16];
    #pragma unroll
    for (int j = 0; j < 4; ++j) {
        #pragma unroll
        for (int i = 0; i < 4; ++i) {
            int g = j * 4 + i;
            int k = j * 128 + lane * 4 + i;
            float4 tv = *(const float4*)(T + (long long)k * M_TAGS + c0);
            tm01[g] = pack2(tv.x, tv.y);
            tm23[g] = pack2(tv.z, tv.w);
        }
    }

    const uint32_t abase   = smem_u32(&A[0][0]);
    const uint32_t mypeer  = mapa_u32(abase, (uint32_t)(lane & 15));
    const uint32_t col_off = (uint32_t)(c0 << 2);

    float log_acc = 0.f;
    int   budget  = 1 << 25;

    // ---- ext for peel steps t=1..3 and first block t=4..7 ----
    const float* extp = g_ext + c0;
    float4 e1 = *(const float4*)(extp + 1 * M_TAGS);
    float4 e2 = *(const float4*)(extp + 2 * M_TAGS);
    float4 e3 = *(const float4*)(extp + 3 * M_TAGS);
    float4 n0 = *(const float4*)(extp + 4 * M_TAGS);
    float4 n1 = *(const float4*)(extp + 5 * M_TAGS);
    float4 n2 = *(const float4*)(extp + 6 * M_TAGS);
    float4 n3 = *(const float4*)(extp + 7 * M_TAGS);

    // ---- peel t = 1, 2, 3 (pb = 0, no renorm) ----
    STEP(1, 0u, e1, false);
    STEP(2, 0u, e2, false);
    STEP(3, 0u, e3, false);

    // ---- main blocks: u = 1..1023, t = 4u .. 4u+3 ----
    for (int u = 1; u <= 1023; ++u) {
        const uint32_t pb = (uint32_t)(u & 1);
        float4 b0 = n0, b1 = n1, b2 = n2, b3 = n3;
        if (u < 1023) {                       // prefetch next block (off-chain)
            const float* np = extp + (long long)(4 * u + 4) * M_TAGS;
            n0 = *(const float4*)(np);
            n1 = *(const float4*)(np + M_TAGS);
            n2 = *(const float4*)(np + 2 * M_TAGS);
            n3 = *(const float4*)(np + 3 * M_TAGS);
        }
        const bool renorm = ((u & 63) == 0);
        STEP(0, pb, b0, renorm);
        STEP(1, pb, b1, false);
        STEP(2, pb, b2, false);
        STEP(3, pb, b3, false);
    }

    // ---- finalize: rank 0, warp 0 (t = 4095, stored parity = 1) ----
    if (rank == 0 && w == 0) {
        const uint32_t ps = 1u << 31;
        const uint32_t rbase = abase + (3u << 11) + (lane << 4);
        float4 v0, v1, v2, v3;
        for (;;) {
            v0 = lds_vol_v4(rbase);
            v1 = lds_vol_v4(rbase + 512);
            v2 = lds_vol_v4(rbase + 1024);
            v3 = lds_vol_v4(rbase + 1536);
            uint32_t yy = (__float_as_uint(v0.x) ^ ps) | (__float_as_uint(v1.x) ^ ps)
                        | (__float_as_uint(v2.x) ^ ps) | (__float_as_uint(v3.x) ^ ps);
            if (__all_sync(FULLMASK, (int)yy >= 0)) break;
            if (--budget < 0) break;
        }
        float ss = ((v0.x + v0.y) + (v0.z + v0.w))
                 + ((v1.x + v1.y) + (v1.z + v1.w))
                 + ((v2.x + v2.y) + (v2.z + v2.w))
                 + ((v3.x + v3.y) + (v3.z + v3.w));
        #pragma unroll
        for (int off = 16; off; off >>= 1)
            ss += __shfl_xor_sync(FULLMASK, ss, off);
        if (lane == 0) {
            // ln(128) = 7*ln(2) = 4.852030263919617
            double logz = (double)logf(fabsf(ss))
                        + 4095.0 * 4.852030263919617
                        + (double)log_acc;
            out[0] = (float)(logz - (double)g_phipath);
        }
    }

    // ---- exit fence ----
    cluster_barrier();
}

// =====================================================================
extern "C" void kernel_launch(void* const* d_in, const int* in_sizes, int n_in,
                              void* d_out, int out_size)
{
    const float* T     = (const float*)d_in[0];
    const float* E     = (const float*)d_in[1];
    const float* Eprev = (const float*)d_in[2];
    const float* Enext = (const float*)d_in[3];
    const float* Cap   = (const float*)d_in[4];
    const int*   x     = (const int*)d_in[5];
    const int*   y     = (const int*)d_in[6];
    const int*   upper = (const int*)d_in[7];
    float*       out   = (float*)d_out;
    (void)in_sizes; (void)n_in; (void)out_size;

    cudaFuncSetAttribute(crf_chain_kernel,
                         cudaFuncAttributeNonPortableClusterSizeAllowed, 1);

    const int ext_blocks = (L_SEQ * M_TAGS + 255) / 256;   // 8192
    crf_init_kernel<<<2 + ext_blocks, 256>>>(T, E, Eprev, Enext, Cap, x, y, upper);
    crf_chain_kernel<<<NCTA, THREADS>>>(T, out);
}